// round 7
// baseline (speedup 1.0000x reference)
#include <cuda_runtime.h>
#include <math.h>

#define HW 4096
typedef unsigned long long ull;

__device__ float g_enc[64 * HW];
__device__ float g_feat[256 * HW];
__device__ float g_fq[HW * 256];
__device__ float g_fk[HW * 256];
__device__ float g_fv[HW * 256];
__device__ float g_off1[HW * 256];
__device__ float g_act[HW * 256];
__device__ float g_offmap[HW * 98];
__device__ float g_attn[4096 * 49 * 8];
__device__ int   g_kidx[4096 * 49];
__device__ float g_skipv[4096 * 3];
__device__ float g_Wi1T[12546 * 256];
__device__ float g_Wc1T[98 * 256];
__device__ float g_Wc2T[256 * 49];

// ---- packed f32x2 helpers (FFMA2: 2 fp32 FMAs per instr, rn rounding) ------
__device__ __forceinline__ ull pk(float lo, float hi) {
    ull r; asm("mov.b64 %0, {%1, %2};" : "=l"(r) : "f"(lo), "f"(hi)); return r;
}
__device__ __forceinline__ void fma2(ull& d, ull a, ull b) {
    asm("fma.rn.f32x2 %0, %1, %2, %0;" : "+l"(d) : "l"(a), "l"(b));
}
__device__ __forceinline__ float2 upk(ull v) {
    float2 f; asm("mov.b64 {%0, %1}, %2;" : "=f"(f.x), "=f"(f.y) : "l"(v)); return f;
}

// ---------------- generic tiled transpose: src[rows][cols] -> dst[cols][rows]
__global__ void transpose_kernel(const float* __restrict__ src, float* __restrict__ dst,
                                 int rows, int cols)
{
    __shared__ float tile[32][33];
    int c0 = blockIdx.x * 32, r0 = blockIdx.y * 32;
    int tx = threadIdx.x, ty = threadIdx.y;
#pragma unroll
    for (int i = 0; i < 32; i += 8) {
        int r = r0 + ty + i, c = c0 + tx;
        tile[ty + i][tx] = (r < rows && c < cols) ? src[r * cols + c] : 0.f;
    }
    __syncthreads();
#pragma unroll
    for (int i = 0; i < 32; i += 8) {
        int r = c0 + ty + i, c = r0 + tx;
        if (r < cols && c < rows) dst[r * rows + c] = tile[tx][ty + i];
    }
}

// ---------------- 3x3 conv pad1, f32x2. grid(4,4,COUT/16), block 128 --------
template <int CIN, int COUT, bool RELU, bool PIXMAJOR>
__global__ void __launch_bounds__(128) conv3x3_kernel(
    const float* __restrict__ in, const float* __restrict__ W,
    const float* __restrict__ B, float* __restrict__ out)
{
    __shared__ float s_in[18 * 18];
    __shared__ float s_w[16 * 12];   // padded rows: 9 taps in 12 slots
    const int tid = threadIdx.x;
    const int cog = tid >> 6, qid = tid & 63;
    const int qy = qid >> 3, qx = qid & 7;
    const int ty0 = blockIdx.y * 16, tx0 = blockIdx.x * 16;
    const int cobase = blockIdx.z * 16;

    int l_src[3]; bool l_ok[3];
#pragma unroll
    for (int t = 0; t < 3; t++) {
        int i = tid + t * 128; l_ok[t] = false; l_src[t] = 0;
        if (i < 324) {
            int r = i / 18, c = i % 18;
            int y = ty0 + r - 1, x = tx0 + c - 1;
            l_ok[t] = (y >= 0 && y < 64 && x >= 0 && x < 64);
            l_src[t] = y * 64 + x;
        }
    }
    // acc2[oy][j]: packed pair over ox = (0,1)
    ull acc2[2][8];
#pragma unroll
    for (int a = 0; a < 2; a++)
#pragma unroll
        for (int j = 0; j < 8; j++) acc2[a][j] = 0ull;

    for (int ci = 0; ci < CIN; ci++) {
        const float* inc = in + ci * HW;
#pragma unroll
        for (int t = 0; t < 3; t++) {
            int i = tid + t * 128;
            if (i < 324) s_in[i] = l_ok[t] ? inc[l_src[t]] : 0.f;
        }
#pragma unroll
        for (int i = tid; i < 144; i += 128)
            s_w[(i / 9) * 12 + i % 9] = W[((cobase + i / 9) * CIN + ci) * 9 + i % 9];
        __syncthreads();
        float p[4][4];
#pragma unroll
        for (int r = 0; r < 4; r++)
#pragma unroll
            for (int c = 0; c < 4; c++)
                p[r][c] = s_in[(qy * 2 + r) * 18 + qx * 2 + c];
        // horizontal pair packs (p[r][kx], p[r][kx+1])
        ull pp[4][3];
#pragma unroll
        for (int r = 0; r < 4; r++)
#pragma unroll
            for (int kx = 0; kx < 3; kx++) pp[r][kx] = pk(p[r][kx], p[r][kx + 1]);
#pragma unroll
        for (int j = 0; j < 8; j++) {
            const float* w = &s_w[(cog * 8 + j) * 12];
            float4 wa = *(const float4*)w;
            float4 wb = *(const float4*)(w + 4);
            float w8 = w[8];
            ull wd[9];
            wd[0] = pk(wa.x, wa.x); wd[1] = pk(wa.y, wa.y); wd[2] = pk(wa.z, wa.z);
            wd[3] = pk(wa.w, wa.w); wd[4] = pk(wb.x, wb.x); wd[5] = pk(wb.y, wb.y);
            wd[6] = pk(wb.z, wb.z); wd[7] = pk(wb.w, wb.w); wd[8] = pk(w8, w8);
#pragma unroll
            for (int ky = 0; ky < 3; ky++)
#pragma unroll
                for (int kx = 0; kx < 3; kx++) {
                    fma2(acc2[0][j], pp[ky][kx],     wd[ky * 3 + kx]);
                    fma2(acc2[1][j], pp[ky + 1][kx], wd[ky * 3 + kx]);
                }
        }
        __syncthreads();
    }
#pragma unroll
    for (int oy = 0; oy < 2; oy++) {
#pragma unroll
        for (int j = 0; j < 8; j++) {
            float2 v = upk(acc2[oy][j]);
            int co = cobase + cog * 8 + j;
            float bv = B[co];
            float r0 = v.x + bv, r1 = v.y + bv;
            if (RELU) { r0 = fmaxf(r0, 0.f); r1 = fmaxf(r1, 0.f); }
            int pix0 = (ty0 + qy * 2 + oy) * 64 + tx0 + qx * 2;
            if (PIXMAJOR) {
                out[pix0 * COUT + co] = r0;
                out[(pix0 + 1) * COUT + co] = r1;
            } else {
                out[co * HW + pix0] = r0;
                out[co * HW + pix0 + 1] = r1;
            }
        }
    }
}

// ---------------- grouped 5x5 pad2, groups 8. grid(4,4,8), block 256 --------
__global__ void __launch_bounds__(256) conv5x5g_kernel(
    const float* __restrict__ in, const float* __restrict__ W,
    const float* __restrict__ B, float* __restrict__ out)
{
    __shared__ float s_in[20 * 20];
    __shared__ float s_w[32 * 25];
    const int tid = threadIdx.x;
    const int cog = tid >> 6, qid = tid & 63;
    const int qy = qid >> 3, qx = qid & 7;
    const int ty0 = blockIdx.y * 16, tx0 = blockIdx.x * 16;
    const int grp = blockIdx.z;

    int l_src[2]; bool l_ok[2];
#pragma unroll
    for (int t = 0; t < 2; t++) {
        int i = tid + t * 256; l_ok[t] = false; l_src[t] = 0;
        if (i < 400) {
            int r = i / 20, c = i % 20;
            int y = ty0 + r - 2, x = tx0 + c - 2;
            l_ok[t] = (y >= 0 && y < 64 && x >= 0 && x < 64);
            l_src[t] = y * 64 + x;
        }
    }
    float acc[2][2][8];
#pragma unroll
    for (int a = 0; a < 2; a++)
#pragma unroll
        for (int b = 0; b < 2; b++)
#pragma unroll
            for (int j = 0; j < 8; j++) acc[a][b][j] = 0.f;

    for (int cil = 0; cil < 32; cil++) {
        const float* inc = in + (grp * 32 + cil) * HW;
#pragma unroll
        for (int t = 0; t < 2; t++) {
            int i = tid + t * 256;
            if (i < 400) s_in[i] = l_ok[t] ? inc[l_src[t]] : 0.f;
        }
        for (int i = tid; i < 800; i += 256)
            s_w[i] = W[((grp * 32 + i / 25) * 32 + cil) * 25 + i % 25];
        __syncthreads();
        float p[6][6];
#pragma unroll
        for (int r = 0; r < 6; r++)
#pragma unroll
            for (int c = 0; c < 6; c++)
                p[r][c] = s_in[(qy * 2 + r) * 20 + qx * 2 + c];
#pragma unroll
        for (int j = 0; j < 8; j++) {
            const float* w = &s_w[(cog * 8 + j) * 25];
#pragma unroll
            for (int oy = 0; oy < 2; oy++)
#pragma unroll
                for (int ox = 0; ox < 2; ox++) {
                    float s = 0.f;
#pragma unroll
                    for (int ky = 0; ky < 5; ky++)
#pragma unroll
                        for (int kx = 0; kx < 5; kx++)
                            s += w[ky * 5 + kx] * p[oy + ky][ox + kx];
                    acc[oy][ox][j] += s;
                }
        }
        __syncthreads();
    }
#pragma unroll
    for (int oy = 0; oy < 2; oy++)
#pragma unroll
        for (int ox = 0; ox < 2; ox++) {
            int pix = (ty0 + qy * 2 + oy) * 64 + tx0 + qx * 2 + ox;
#pragma unroll
            for (int j = 0; j < 8; j++) {
                int co = grp * 32 + cog * 8 + j;
                out[pix * 256 + co] = acc[oy][ox][j] + B[co];
            }
        }
}

// ---------------- LayerNorm + exact GELU. grid 512, block 256 ---------------
__global__ void __launch_bounds__(256) ln_gelu_kernel(
    const float* __restrict__ in, const float* __restrict__ gam,
    const float* __restrict__ bet, float* __restrict__ out)
{
    const int lane = threadIdx.x & 31, wid = threadIdx.x >> 5;
    const int pix = blockIdx.x * 8 + wid;
    float x[8];
#pragma unroll
    for (int i = 0; i < 8; i++) x[i] = in[pix * 256 + i * 32 + lane];
    float s = 0.f;
#pragma unroll
    for (int i = 0; i < 8; i++) s += x[i];
#pragma unroll
    for (int o = 16; o; o >>= 1) s += __shfl_xor_sync(0xffffffffu, s, o);
    float mu = s * (1.f / 256.f);
    float d = 0.f;
#pragma unroll
    for (int i = 0; i < 8; i++) { float t = x[i] - mu; d += t * t; }
#pragma unroll
    for (int o = 16; o; o >>= 1) d += __shfl_xor_sync(0xffffffffu, d, o);
    float inv = rsqrtf(d * (1.f / 256.f) + 1e-5f);
#pragma unroll
    for (int i = 0; i < 8; i++) {
        int c = i * 32 + lane;
        float y = (x[i] - mu) * inv * gam[c] + bet[c];
        out[pix * 256 + c] = 0.5f * y * (1.f + erff(y * 0.70710678118654752f));
    }
}

// ---------------- 1x1 conv 256->98. grid 128, block 128 ---------------------
__global__ void __launch_bounds__(128) conv1x1_kernel(
    const float* __restrict__ act, const float* __restrict__ W2, float* __restrict__ out)
{
    __shared__ float s_act[32 * 256];
    const int tid = threadIdx.x;
    const int pb = blockIdx.x * 32;
    const float4* src = (const float4*)(act + pb * 256);
    float4* dst = (float4*)s_act;
    for (int i = tid; i < 32 * 64; i += 128) dst[i] = src[i];
    __syncthreads();
    if (tid < 98) {
        float acc[32];
#pragma unroll
        for (int p = 0; p < 32; p++) acc[p] = 0.f;
        for (int c = 0; c < 256; c++) {
            float w = W2[tid * 256 + c];
#pragma unroll
            for (int p = 0; p < 32; p++) acc[p] += w * s_act[p * 256 + c];
        }
#pragma unroll
        for (int p = 0; p < 32; p++) out[(pb + p) * 98 + tid] = acc[p];
    }
}

// ---------------- per-query prep. grid 4096, block 256 ----------------------
__global__ void __launch_bounds__(256) qprep_kernel(
    const float* __restrict__ coord, const float* __restrict__ inp,
    const float* __restrict__ bc1, const float* __restrict__ bc2)
{
    __shared__ float s_q[256];
    __shared__ float s_rel[98];
    __shared__ float s_av[49 * 8];
    __shared__ float s_wc[49];
    __shared__ float s_h[256];
    __shared__ int   s_kidx[49];

    const int q = blockIdx.x;
    const int tid = threadIdx.x, lane = tid & 31, wid = tid >> 5;
    const float cy = coord[q * 2 + 0], cx = coord[q * 2 + 1];
    const float gx = ((cx + 1.f) * 64.f - 1.f) * 0.5f;
    const float gy = ((cy + 1.f) * 64.f - 1.f) * 0.5f;

    { // bilinear fq sample (zeros pad), thread == channel
        float x0f = floorf(gx), y0f = floorf(gy);
        int x0 = (int)x0f, y0 = (int)y0f;
        float wx = gx - x0f, wy = gy - y0f;
        float a = 0.f;
#pragma unroll
        for (int t = 0; t < 4; t++) {
            int ix = x0 + (t & 1), iy = y0 + (t >> 1);
            float w = ((t & 1) ? wx : 1.f - wx) * ((t >> 1) ? wy : 1.f - wy);
            bool m = (ix >= 0 && ix < 64 && iy >= 0 && iy < 64);
            int pc = min(max(iy, 0), 63) * 64 + min(max(ix, 0), 63);
            float v = g_fq[pc * 256 + tid];
            a += m ? w * v : 0.f;
        }
        s_q[tid] = a;
    }

    const int ix0 = __float2int_rn(gx), iy0 = __float2int_rn(gy);
    const bool m0 = (ix0 >= 0 && ix0 < 64 && iy0 >= 0 && iy0 < 64);
    const int pix0 = min(max(iy0, 0), 63) * 64 + min(max(ix0, 0), 63);
    const float yb = m0 ? (-1.f + 0.015625f + 0.03125f * (float)iy0) : 0.f;
    const float xb = m0 ? (-1.f + 0.015625f + 0.03125f * (float)ix0) : 0.f;

    if (tid < 49) {
        const int k = tid;
        float o0 = m0 ? g_offmap[pix0 * 98 + 2 * k] : 0.f;
        float o1 = m0 ? g_offmap[pix0 * 98 + 2 * k + 1] : 0.f;
        float sy = yb + (float)(k / 7 - 3) * 0.03125f + tanhf(o0) * (2.f / 63.f);
        float sx = xb + (float)(k % 7 - 3) * 0.03125f + tanhf(o1) * (2.f / 63.f);
        s_rel[2 * k] = (cy - sy) * 64.f;
        s_rel[2 * k + 1] = (cx - sx) * 64.f;
        float gky = ((sy + 1.f) * 64.f - 1.f) * 0.5f;
        float gkx = ((sx + 1.f) * 64.f - 1.f) * 0.5f;
        int iky = __float2int_rn(gky), ikx = __float2int_rn(gkx);
        bool ok = (ikx >= 0 && ikx < 64 && iky >= 0 && iky < 64);
        s_kidx[k] = ok ? iky * 64 + ikx : -1;
        g_kidx[q * 49 + k] = s_kidx[k];
    }
    __syncthreads();

    // attn_val: warp per k, lane -> (h = lane>>2, part = lane&3)
    for (int k = wid; k < 49; k += 8) {
        int pix = s_kidx[k];
        int h = lane >> 2, part = lane & 3;
        float s = 0.f;
        if (pix >= 0) {
            const float* fr = g_fk + pix * 256 + h * 32 + part * 8;
            const float* qr = s_q + h * 32 + part * 8;
#pragma unroll
            for (int i = 0; i < 8; i++) s += fr[i] * qr[i];
        }
        s += __shfl_xor_sync(0xffffffffu, s, 1);
        s += __shfl_xor_sync(0xffffffffu, s, 2);
        if (part == 0) s_av[k * 8 + h] = s * 0.17677669529663687f;
    }

    { // coord MLP layer 1 (98->256), thread == hidden unit (coalesced Wc1T)
        float h1 = bc1[tid];
        for (int i = 0; i < 98; i++) h1 += g_Wc1T[i * 256 + tid] * s_rel[i];
        s_h[tid] = fmaxf(h1, 0.f);
    }
    __syncthreads();

    if (tid < 49) {
        float w = bc2[tid];
        for (int j = 0; j < 256; j++) w += g_Wc2T[j * 49 + tid] * s_h[j];
        s_wc[tid] = w;
    }
    if (tid >= 64 && tid < 67) { // skip: bilinear border
        const int c = tid - 64;
        float gxc = fminf(fmaxf(gx, 0.f), 63.f), gyc = fminf(fmaxf(gy, 0.f), 63.f);
        float x0f = floorf(gxc), y0f = floorf(gyc);
        int x0 = (int)x0f, y0 = (int)y0f;
        float wx = gxc - x0f, wy = gyc - y0f;
        int x1 = min(x0 + 1, 63), y1 = min(y0 + 1, 63);
        const float* I = inp + c * HW;
        g_skipv[q * 3 + c] = (1.f - wx) * (1.f - wy) * I[y0 * 64 + x0]
                           + wx * (1.f - wy) * I[y0 * 64 + x1]
                           + (1.f - wx) * wy * I[y1 * 64 + x0]
                           + wx * wy * I[y1 * 64 + x1];
    }
    __syncthreads();

    if (tid < 8) { // softmax over k per head
        const int h = tid;
        float mx = -1e30f;
        for (int k = 0; k < 49; k++) mx = fmaxf(mx, s_wc[k] + s_av[k * 8 + h]);
        float sum = 0.f;
        for (int k = 0; k < 49; k++) {
            float e = expf(s_wc[k] + s_av[k * 8 + h] - mx);
            s_av[k * 8 + h] = e;
            sum += e;
        }
        float inv = 1.f / sum;
        for (int k = 0; k < 49; k++) g_attn[(q * 49 + k) * 8 + h] = s_av[k * 8 + h] * inv;
    }
}

// ---------------- big GEMM (f32x2) + final MLP + skip. grid 128, block 128 --
// warp = one 8q group covering all 256 j -> a reads are smem broadcasts.
// smem: s_a[256][36] (9216 f) + s_w[32][256] (8192 f) = 69632 B
__global__ void __launch_bounds__(128) gemm_kernel(
    const float* __restrict__ cell, const float* __restrict__ bi1,
    const float* __restrict__ Wi2, const float* __restrict__ bi2,
    float* __restrict__ out)
{
    extern __shared__ float sm[];
    float* s_a = sm;
    float* s_w = sm + 9216;
    const int t = threadIdx.x;
    const int qb = blockIdx.x * 32;
    const int bq = t >> 2, h0 = (t & 3) * 2;      // a-build roles: 32q x 2h
    const int q0 = (t >> 5) * 8, j0 = (t & 31) * 8; // compute microtile 8q x 8j

    // acc2[q][jp]: packed pair over j = (j0+2jp, j0+2jp+1)
    ull acc2[8][4];
#pragma unroll
    for (int p = 0; p < 8; p++)
#pragma unroll
        for (int jp = 0; jp < 4; jp++) acc2[p][jp] = 0ull;

    for (int k = 0; k < 49; k++) {
        __syncthreads();
        int pix = g_kidx[(qb + bq) * 49 + k];
        const float4* frbase = (const float4*)(g_fv + (pix < 0 ? 0 : pix) * 256);
#pragma unroll
        for (int hh = h0; hh < h0 + 2; hh++) {
            float aw = g_attn[((qb + bq) * 49 + k) * 8 + hh];
            const float4* fr = frbase + hh * 8;
#pragma unroll
            for (int i = 0; i < 8; i++) {
                float4 v = fr[i];
                if (pix < 0) v = make_float4(0.f, 0.f, 0.f, 0.f);
                int c = hh * 32 + i * 4;
                s_a[(c + 0) * 36 + bq] = v.x * aw;
                s_a[(c + 1) * 36 + bq] = v.y * aw;
                s_a[(c + 2) * 36 + bq] = v.z * aw;
                s_a[(c + 3) * 36 + bq] = v.w * aw;
            }
        }
        for (int sub = 0; sub < 8; sub++) {
            __syncthreads();
            const float4* src = (const float4*)(g_Wi1T + (k * 256 + sub * 32) * 256);
            float4* dw = (float4*)s_w;
#pragma unroll
            for (int i = 0; i < 16; i++) dw[t + i * 128] = src[t + i * 128];
            __syncthreads();
#pragma unroll 2
            for (int cc = 0; cc < 32; cc++) {
                const float* ar = s_a + (sub * 32 + cc) * 36 + q0;
                float4 a0 = *(const float4*)ar;
                float4 a1 = *(const float4*)(ar + 4);
                ull ad[8];
                ad[0] = pk(a0.x, a0.x); ad[1] = pk(a0.y, a0.y);
                ad[2] = pk(a0.z, a0.z); ad[3] = pk(a0.w, a0.w);
                ad[4] = pk(a1.x, a1.x); ad[5] = pk(a1.y, a1.y);
                ad[6] = pk(a1.z, a1.z); ad[7] = pk(a1.w, a1.w);
                const ulonglong2* wr = (const ulonglong2*)(s_w + cc * 256 + j0);
                ulonglong2 wA = wr[0];   // j pairs (j0,j0+1),(j0+2,j0+3)
                ulonglong2 wB = wr[1];   // j pairs (j0+4,j0+5),(j0+6,j0+7)
#pragma unroll
                for (int p = 0; p < 8; p++) {
                    fma2(acc2[p][0], ad[p], wA.x);
                    fma2(acc2[p][1], ad[p], wA.y);
                    fma2(acc2[p][2], ad[p], wB.x);
                    fma2(acc2[p][3], ad[p], wB.y);
                }
            }
        }
    }
    __syncthreads();

    // unpack accumulators: accf[p][j], j relative to j0
    float accf[8][8];
#pragma unroll
    for (int p = 0; p < 8; p++)
#pragma unroll
        for (int jp = 0; jp < 4; jp++) {
            float2 v = upk(acc2[p][jp]);
            accf[p][2 * jp] = v.x;
            accf[p][2 * jp + 1] = v.y;
        }

    // epilogue: bias + cell tail + relu -> s_h (reuses s_a region)
    float* s_h = sm; // [32][260]
    float bb[8], w0c[8], w1c[8];
    {
        float4 ba = *(const float4*)(bi1 + j0), bbv = *(const float4*)(bi1 + j0 + 4);
        float4 ca = *(const float4*)(g_Wi1T + 12544 * 256 + j0);
        float4 cb = *(const float4*)(g_Wi1T + 12544 * 256 + j0 + 4);
        float4 da = *(const float4*)(g_Wi1T + 12545 * 256 + j0);
        float4 db = *(const float4*)(g_Wi1T + 12545 * 256 + j0 + 4);
        bb[0]=ba.x; bb[1]=ba.y; bb[2]=ba.z; bb[3]=ba.w; bb[4]=bbv.x; bb[5]=bbv.y; bb[6]=bbv.z; bb[7]=bbv.w;
        w0c[0]=ca.x; w0c[1]=ca.y; w0c[2]=ca.z; w0c[3]=ca.w; w0c[4]=cb.x; w0c[5]=cb.y; w0c[6]=cb.z; w0c[7]=cb.w;
        w1c[0]=da.x; w1c[1]=da.y; w1c[2]=da.z; w1c[3]=da.w; w1c[4]=db.x; w1c[5]=db.y; w1c[6]=db.z; w1c[7]=db.w;
    }
#pragma unroll
    for (int p = 0; p < 8; p++) {
        int q = qb + q0 + p;
        float ry = cell[q * 2 + 0] * 64.f, rx = cell[q * 2 + 1] * 64.f;
        float h[8];
#pragma unroll
        for (int j = 0; j < 8; j++)
            h[j] = fmaxf(accf[p][j] + bb[j] + w0c[j] * ry + w1c[j] * rx, 0.f);
        float* dst = s_h + (q0 + p) * 260 + j0;
        *(float4*)dst = make_float4(h[0], h[1], h[2], h[3]);
        *(float4*)(dst + 4) = make_float4(h[4], h[5], h[6], h[7]);
    }
    float* s_w2 = sm + 9216;
    for (int i = t; i < 768; i += 128) s_w2[i] = Wi2[i];
    __syncthreads();

    if (t < 96) {
        int q = t / 3, c = t % 3;
        float s = 0.f;
        for (int j = 0; j < 256; j++) s += s_h[q * 260 + j] * s_w2[c * 256 + j];
        out[(qb + q) * 3 + c] = s + bi2[c] + g_skipv[(qb + q) * 3 + c];
    }
}

// ---------------- host ------------------------------------------------------
extern "C" void kernel_launch(void* const* d_in, const int* in_sizes, int n_in,
                              void* d_out, int out_size)
{
    const float* inp   = (const float*)d_in[0];
    const float* coord = (const float*)d_in[1];
    const float* cell  = (const float*)d_in[2];
    const float* W_enc = (const float*)d_in[3];
    const float* b_enc = (const float*)d_in[4];
    const float* W_ch  = (const float*)d_in[5];
    const float* b_ch  = (const float*)d_in[6];
    const float* W_q   = (const float*)d_in[7];
    const float* b_q   = (const float*)d_in[8];
    const float* W_k   = (const float*)d_in[9];
    const float* b_k   = (const float*)d_in[10];
    const float* W_v   = (const float*)d_in[11];
    const float* b_v   = (const float*)d_in[12];
    const float* W_off1= (const float*)d_in[13];
    const float* b_off1= (const float*)d_in[14];
    const float* ln_g  = (const float*)d_in[15];
    const float* ln_b  = (const float*)d_in[16];
    const float* W_off2= (const float*)d_in[17];
    const float* Wc1   = (const float*)d_in[18];
    const float* bc1   = (const float*)d_in[19];
    const float* Wc2   = (const float*)d_in[20];
    const float* bc2   = (const float*)d_in[21];
    const float* Wi1   = (const float*)d_in[22];
    const float* bi1   = (const float*)d_in[23];
    const float* Wi2   = (const float*)d_in[24];
    const float* bi2   = (const float*)d_in[25];
    float* out = (float*)d_out;

    void* p;
    cudaGetSymbolAddress(&p, g_enc);    float* enc = (float*)p;
    cudaGetSymbolAddress(&p, g_feat);   float* feat = (float*)p;
    cudaGetSymbolAddress(&p, g_fq);     float* fq = (float*)p;
    cudaGetSymbolAddress(&p, g_fk);     float* fk = (float*)p;
    cudaGetSymbolAddress(&p, g_fv);     float* fv = (float*)p;
    cudaGetSymbolAddress(&p, g_off1);   float* off1 = (float*)p;
    cudaGetSymbolAddress(&p, g_act);    float* act = (float*)p;
    cudaGetSymbolAddress(&p, g_offmap); float* offmap = (float*)p;
    cudaGetSymbolAddress(&p, g_Wi1T);   float* wi1t = (float*)p;
    cudaGetSymbolAddress(&p, g_Wc1T);   float* wc1t = (float*)p;
    cudaGetSymbolAddress(&p, g_Wc2T);   float* wc2t = (float*)p;

    dim3 tb(32, 8);
    transpose_kernel<<<dim3(393, 8), tb>>>(Wi1, wi1t, 256, 12546);
    transpose_kernel<<<dim3(4, 8), tb>>>(Wc1, wc1t, 256, 98);
    transpose_kernel<<<dim3(8, 2), tb>>>(Wc2, wc2t, 49, 256);

    conv3x3_kernel<3, 64, true, false><<<dim3(4, 4, 4), 128>>>(inp, W_enc, b_enc, enc);
    conv3x3_kernel<64, 256, false, false><<<dim3(4, 4, 16), 128>>>(enc, W_ch, b_ch, feat);
    conv3x3_kernel<256, 256, false, true><<<dim3(4, 4, 16), 128>>>(feat, W_q, b_q, fq);
    conv3x3_kernel<256, 256, false, true><<<dim3(4, 4, 16), 128>>>(feat, W_k, b_k, fk);
    conv3x3_kernel<256, 256, false, true><<<dim3(4, 4, 16), 128>>>(feat, W_v, b_v, fv);
    conv5x5g_kernel<<<dim3(4, 4, 8), 256>>>(feat, W_off1, b_off1, off1);
    ln_gelu_kernel<<<512, 256>>>(off1, ln_g, ln_b, act);
    conv1x1_kernel<<<128, 128>>>(act, W_off2, offmap);
    qprep_kernel<<<4096, 256>>>(coord, inp, bc1, bc2);

    cudaFuncSetAttribute(gemm_kernel, cudaFuncAttributeMaxDynamicSharedMemorySize, 69632);
    gemm_kernel<<<128, 128, 69632>>>(cell, bi1, Wi2, bi2, out);
}

// round 8
// speedup vs baseline: 1.4426x; 1.4426x over previous
#include <cuda_runtime.h>
#include <math.h>

#define HW 4096

__device__ float g_enc[64 * HW];
__device__ float g_feat[256 * HW];
__device__ float g_fq[HW * 256];
__device__ float g_fk[HW * 256];
__device__ float g_fv[HW * 256];
__device__ float g_off1[HW * 256];
__device__ float g_act[HW * 256];
__device__ float g_offmap[HW * 98];
__device__ float g_attn[4096 * 49 * 8];
__device__ int   g_kidx[4096 * 49];
__device__ float g_skipv[4096 * 3];
__device__ float g_Wi1T[12546 * 256];
__device__ float g_Wc1T[98 * 256];
__device__ float g_Wc2T[256 * 49];

__device__ __forceinline__ float totf32(float x) {
    float r; asm("cvt.rna.tf32.f32 %0, %1;" : "=f"(r) : "f"(x)); return r;
}
__device__ __forceinline__ void mma_tf32(float* c, const unsigned* a, const unsigned* b) {
    asm volatile("mma.sync.aligned.m16n8k8.row.col.f32.tf32.tf32.f32 "
        "{%0,%1,%2,%3}, {%4,%5,%6,%7}, {%8,%9}, {%0,%1,%2,%3};"
        : "+f"(c[0]), "+f"(c[1]), "+f"(c[2]), "+f"(c[3])
        : "r"(a[0]), "r"(a[1]), "r"(a[2]), "r"(a[3]), "r"(b[0]), "r"(b[1]));
}

// ---------------- transpose: src[rows][cols] -> dst[cols][rows] -------------
// tf32!=0: round values to tf32 (rna) on store (for tensor-core consumption)
__global__ void transpose_kernel(const float* __restrict__ src, float* __restrict__ dst,
                                 int rows, int cols, int tf32)
{
    __shared__ float tile[32][33];
    int c0 = blockIdx.x * 32, r0 = blockIdx.y * 32;
    int tx = threadIdx.x, ty = threadIdx.y;
#pragma unroll
    for (int i = 0; i < 32; i += 8) {
        int r = r0 + ty + i, c = c0 + tx;
        tile[ty + i][tx] = (r < rows && c < cols) ? src[r * cols + c] : 0.f;
    }
    __syncthreads();
#pragma unroll
    for (int i = 0; i < 32; i += 8) {
        int r = c0 + ty + i, c = r0 + tx;
        if (r < cols && c < rows) {
            float v = tile[tx][ty + i];
            if (tf32) v = totf32(v);
            dst[r * rows + c] = v;
        }
    }
}

// ---------------- 3x3 conv pad1. grid(4,4,COUT/16), block 128 ---------------
template <int CIN, int COUT, bool RELU, bool PIXMAJOR>
__global__ void __launch_bounds__(128) conv3x3_kernel(
    const float* __restrict__ in, const float* __restrict__ W,
    const float* __restrict__ B, float* __restrict__ out)
{
    __shared__ float s_in[18 * 18];
    __shared__ float s_w[16 * 9];
    const int tid = threadIdx.x;
    const int cog = tid >> 6, qid = tid & 63;
    const int qy = qid >> 3, qx = qid & 7;
    const int ty0 = blockIdx.y * 16, tx0 = blockIdx.x * 16;
    const int cobase = blockIdx.z * 16;

    int l_src[3]; bool l_ok[3];
#pragma unroll
    for (int t = 0; t < 3; t++) {
        int i = tid + t * 128; l_ok[t] = false; l_src[t] = 0;
        if (i < 324) {
            int r = i / 18, c = i % 18;
            int y = ty0 + r - 1, x = tx0 + c - 1;
            l_ok[t] = (y >= 0 && y < 64 && x >= 0 && x < 64);
            l_src[t] = y * 64 + x;
        }
    }
    float acc[2][2][8];
#pragma unroll
    for (int a = 0; a < 2; a++)
#pragma unroll
        for (int b = 0; b < 2; b++)
#pragma unroll
            for (int j = 0; j < 8; j++) acc[a][b][j] = 0.f;

    for (int ci = 0; ci < CIN; ci++) {
        const float* inc = in + ci * HW;
#pragma unroll
        for (int t = 0; t < 3; t++) {
            int i = tid + t * 128;
            if (i < 324) s_in[i] = l_ok[t] ? inc[l_src[t]] : 0.f;
        }
#pragma unroll
        for (int i = tid; i < 144; i += 128)
            s_w[i] = W[((cobase + i / 9) * CIN + ci) * 9 + i % 9];
        __syncthreads();
        float p[4][4];
#pragma unroll
        for (int r = 0; r < 4; r++)
#pragma unroll
            for (int c = 0; c < 4; c++)
                p[r][c] = s_in[(qy * 2 + r) * 18 + qx * 2 + c];
#pragma unroll
        for (int j = 0; j < 8; j++) {
            const float* w = &s_w[(cog * 8 + j) * 9];
#pragma unroll
            for (int oy = 0; oy < 2; oy++)
#pragma unroll
                for (int ox = 0; ox < 2; ox++)
                    acc[oy][ox][j] += w[0]*p[oy][ox]   + w[1]*p[oy][ox+1]   + w[2]*p[oy][ox+2]
                                    + w[3]*p[oy+1][ox] + w[4]*p[oy+1][ox+1] + w[5]*p[oy+1][ox+2]
                                    + w[6]*p[oy+2][ox] + w[7]*p[oy+2][ox+1] + w[8]*p[oy+2][ox+2];
        }
        __syncthreads();
    }
#pragma unroll
    for (int oy = 0; oy < 2; oy++)
#pragma unroll
        for (int ox = 0; ox < 2; ox++) {
            int pix = (ty0 + qy * 2 + oy) * 64 + tx0 + qx * 2 + ox;
#pragma unroll
            for (int j = 0; j < 8; j++) {
                int co = cobase + cog * 8 + j;
                float v = acc[oy][ox][j] + B[co];
                if (RELU) v = fmaxf(v, 0.f);
                if (PIXMAJOR) out[pix * COUT + co] = v;
                else out[co * HW + pix] = v;
            }
        }
}

// ---------------- grouped 5x5 pad2, groups 8. grid(4,4,8), block 256 --------
__global__ void __launch_bounds__(256) conv5x5g_kernel(
    const float* __restrict__ in, const float* __restrict__ W,
    const float* __restrict__ B, float* __restrict__ out)
{
    __shared__ float s_in[20 * 20];
    __shared__ float s_w[32 * 25];
    const int tid = threadIdx.x;
    const int cog = tid >> 6, qid = tid & 63;
    const int qy = qid >> 3, qx = qid & 7;
    const int ty0 = blockIdx.y * 16, tx0 = blockIdx.x * 16;
    const int grp = blockIdx.z;

    int l_src[2]; bool l_ok[2];
#pragma unroll
    for (int t = 0; t < 2; t++) {
        int i = tid + t * 256; l_ok[t] = false; l_src[t] = 0;
        if (i < 400) {
            int r = i / 20, c = i % 20;
            int y = ty0 + r - 2, x = tx0 + c - 2;
            l_ok[t] = (y >= 0 && y < 64 && x >= 0 && x < 64);
            l_src[t] = y * 64 + x;
        }
    }
    float acc[2][2][8];
#pragma unroll
    for (int a = 0; a < 2; a++)
#pragma unroll
        for (int b = 0; b < 2; b++)
#pragma unroll
            for (int j = 0; j < 8; j++) acc[a][b][j] = 0.f;

    for (int cil = 0; cil < 32; cil++) {
        const float* inc = in + (grp * 32 + cil) * HW;
#pragma unroll
        for (int t = 0; t < 2; t++) {
            int i = tid + t * 256;
            if (i < 400) s_in[i] = l_ok[t] ? inc[l_src[t]] : 0.f;
        }
        for (int i = tid; i < 800; i += 256)
            s_w[i] = W[((grp * 32 + i / 25) * 32 + cil) * 25 + i % 25];
        __syncthreads();
        float p[6][6];
#pragma unroll
        for (int r = 0; r < 6; r++)
#pragma unroll
            for (int c = 0; c < 6; c++)
                p[r][c] = s_in[(qy * 2 + r) * 20 + qx * 2 + c];
#pragma unroll
        for (int j = 0; j < 8; j++) {
            const float* w = &s_w[(cog * 8 + j) * 25];
#pragma unroll
            for (int oy = 0; oy < 2; oy++)
#pragma unroll
                for (int ox = 0; ox < 2; ox++) {
                    float s = 0.f;
#pragma unroll
                    for (int ky = 0; ky < 5; ky++)
#pragma unroll
                        for (int kx = 0; kx < 5; kx++)
                            s += w[ky * 5 + kx] * p[oy + ky][ox + kx];
                    acc[oy][ox][j] += s;
                }
        }
        __syncthreads();
    }
#pragma unroll
    for (int oy = 0; oy < 2; oy++)
#pragma unroll
        for (int ox = 0; ox < 2; ox++) {
            int pix = (ty0 + qy * 2 + oy) * 64 + tx0 + qx * 2 + ox;
#pragma unroll
            for (int j = 0; j < 8; j++) {
                int co = grp * 32 + cog * 8 + j;
                out[pix * 256 + co] = acc[oy][ox][j] + B[co];
            }
        }
}

// ---------------- LayerNorm + exact GELU. grid 512, block 256 ---------------
__global__ void __launch_bounds__(256) ln_gelu_kernel(
    const float* __restrict__ in, const float* __restrict__ gam,
    const float* __restrict__ bet, float* __restrict__ out)
{
    const int lane = threadIdx.x & 31, wid = threadIdx.x >> 5;
    const int pix = blockIdx.x * 8 + wid;
    float x[8];
#pragma unroll
    for (int i = 0; i < 8; i++) x[i] = in[pix * 256 + i * 32 + lane];
    float s = 0.f;
#pragma unroll
    for (int i = 0; i < 8; i++) s += x[i];
#pragma unroll
    for (int o = 16; o; o >>= 1) s += __shfl_xor_sync(0xffffffffu, s, o);
    float mu = s * (1.f / 256.f);
    float d = 0.f;
#pragma unroll
    for (int i = 0; i < 8; i++) { float t = x[i] - mu; d += t * t; }
#pragma unroll
    for (int o = 16; o; o >>= 1) d += __shfl_xor_sync(0xffffffffu, d, o);
    float inv = rsqrtf(d * (1.f / 256.f) + 1e-5f);
#pragma unroll
    for (int i = 0; i < 8; i++) {
        int c = i * 32 + lane;
        float y = (x[i] - mu) * inv * gam[c] + bet[c];
        out[pix * 256 + c] = 0.5f * y * (1.f + erff(y * 0.70710678118654752f));
    }
}

// ---------------- 1x1 conv 256->98. grid 128, block 128 ---------------------
__global__ void __launch_bounds__(128) conv1x1_kernel(
    const float* __restrict__ act, const float* __restrict__ W2, float* __restrict__ out)
{
    __shared__ float s_act[32 * 256];
    const int tid = threadIdx.x;
    const int pb = blockIdx.x * 32;
    const float4* src = (const float4*)(act + pb * 256);
    float4* dst = (float4*)s_act;
    for (int i = tid; i < 32 * 64; i += 128) dst[i] = src[i];
    __syncthreads();
    if (tid < 98) {
        float acc[32];
#pragma unroll
        for (int p = 0; p < 32; p++) acc[p] = 0.f;
        for (int c = 0; c < 256; c++) {
            float w = W2[tid * 256 + c];
#pragma unroll
            for (int p = 0; p < 32; p++) acc[p] += w * s_act[p * 256 + c];
        }
#pragma unroll
        for (int p = 0; p < 32; p++) out[(pb + p) * 98 + tid] = acc[p];
    }
}

// ---------------- per-query prep. grid 4096, block 256 ----------------------
__global__ void __launch_bounds__(256) qprep_kernel(
    const float* __restrict__ coord, const float* __restrict__ inp,
    const float* __restrict__ bc1, const float* __restrict__ bc2)
{
    __shared__ float s_q[256];
    __shared__ float s_rel[98];
    __shared__ float s_av[49 * 8];
    __shared__ float s_wc[49];
    __shared__ float s_h[256];
    __shared__ int   s_kidx[49];

    const int q = blockIdx.x;
    const int tid = threadIdx.x, lane = tid & 31, wid = tid >> 5;
    const float cy = coord[q * 2 + 0], cx = coord[q * 2 + 1];
    const float gx = ((cx + 1.f) * 64.f - 1.f) * 0.5f;
    const float gy = ((cy + 1.f) * 64.f - 1.f) * 0.5f;

    { // bilinear fq sample (zeros pad), thread == channel
        float x0f = floorf(gx), y0f = floorf(gy);
        int x0 = (int)x0f, y0 = (int)y0f;
        float wx = gx - x0f, wy = gy - y0f;
        float a = 0.f;
#pragma unroll
        for (int t = 0; t < 4; t++) {
            int ix = x0 + (t & 1), iy = y0 + (t >> 1);
            float w = ((t & 1) ? wx : 1.f - wx) * ((t >> 1) ? wy : 1.f - wy);
            bool m = (ix >= 0 && ix < 64 && iy >= 0 && iy < 64);
            int pc = min(max(iy, 0), 63) * 64 + min(max(ix, 0), 63);
            float v = g_fq[pc * 256 + tid];
            a += m ? w * v : 0.f;
        }
        s_q[tid] = a;
    }

    const int ix0 = __float2int_rn(gx), iy0 = __float2int_rn(gy);
    const bool m0 = (ix0 >= 0 && ix0 < 64 && iy0 >= 0 && iy0 < 64);
    const int pix0 = min(max(iy0, 0), 63) * 64 + min(max(ix0, 0), 63);
    const float yb = m0 ? (-1.f + 0.015625f + 0.03125f * (float)iy0) : 0.f;
    const float xb = m0 ? (-1.f + 0.015625f + 0.03125f * (float)ix0) : 0.f;

    if (tid < 49) {
        const int k = tid;
        float o0 = m0 ? g_offmap[pix0 * 98 + 2 * k] : 0.f;
        float o1 = m0 ? g_offmap[pix0 * 98 + 2 * k + 1] : 0.f;
        float sy = yb + (float)(k / 7 - 3) * 0.03125f + tanhf(o0) * (2.f / 63.f);
        float sx = xb + (float)(k % 7 - 3) * 0.03125f + tanhf(o1) * (2.f / 63.f);
        s_rel[2 * k] = (cy - sy) * 64.f;
        s_rel[2 * k + 1] = (cx - sx) * 64.f;
        float gky = ((sy + 1.f) * 64.f - 1.f) * 0.5f;
        float gkx = ((sx + 1.f) * 64.f - 1.f) * 0.5f;
        int iky = __float2int_rn(gky), ikx = __float2int_rn(gkx);
        bool ok = (ikx >= 0 && ikx < 64 && iky >= 0 && iky < 64);
        s_kidx[k] = ok ? iky * 64 + ikx : -1;
        g_kidx[q * 49 + k] = s_kidx[k];
    }
    __syncthreads();

    // attn_val: warp per k, lane -> (h = lane>>2, part = lane&3)
    for (int k = wid; k < 49; k += 8) {
        int pix = s_kidx[k];
        int h = lane >> 2, part = lane & 3;
        float s = 0.f;
        if (pix >= 0) {
            const float* fr = g_fk + pix * 256 + h * 32 + part * 8;
            const float* qr = s_q + h * 32 + part * 8;
#pragma unroll
            for (int i = 0; i < 8; i++) s += fr[i] * qr[i];
        }
        s += __shfl_xor_sync(0xffffffffu, s, 1);
        s += __shfl_xor_sync(0xffffffffu, s, 2);
        if (part == 0) s_av[k * 8 + h] = s * 0.17677669529663687f;
    }

    { // coord MLP layer 1 (98->256)
        float h1 = bc1[tid];
        for (int i = 0; i < 98; i++) h1 += g_Wc1T[i * 256 + tid] * s_rel[i];
        s_h[tid] = fmaxf(h1, 0.f);
    }
    __syncthreads();

    if (tid < 49) {
        float w = bc2[tid];
        for (int j = 0; j < 256; j++) w += g_Wc2T[j * 49 + tid] * s_h[j];
        s_wc[tid] = w;
    }
    if (tid >= 64 && tid < 67) { // skip: bilinear border
        const int c = tid - 64;
        float gxc = fminf(fmaxf(gx, 0.f), 63.f), gyc = fminf(fmaxf(gy, 0.f), 63.f);
        float x0f = floorf(gxc), y0f = floorf(gyc);
        int x0 = (int)x0f, y0 = (int)y0f;
        float wx = gxc - x0f, wy = gyc - y0f;
        int x1 = min(x0 + 1, 63), y1 = min(y0 + 1, 63);
        const float* I = inp + c * HW;
        g_skipv[q * 3 + c] = (1.f - wx) * (1.f - wy) * I[y0 * 64 + x0]
                           + wx * (1.f - wy) * I[y0 * 64 + x1]
                           + (1.f - wx) * wy * I[y1 * 64 + x0]
                           + wx * wy * I[y1 * 64 + x1];
    }
    __syncthreads();

    if (tid < 8) { // softmax over k per head
        const int h = tid;
        float mx = -1e30f;
        for (int k = 0; k < 49; k++) mx = fmaxf(mx, s_wc[k] + s_av[k * 8 + h]);
        float sum = 0.f;
        for (int k = 0; k < 49; k++) {
            float e = expf(s_wc[k] + s_av[k * 8 + h] - mx);
            s_av[k * 8 + h] = e;
            sum += e;
        }
        float inv = 1.f / sum;
        for (int k = 0; k < 49; k++) g_attn[(q * 49 + k) * 8 + h] = s_av[k * 8 + h] * inv;
    }
}

// ---------------- big GEMM via tf32 mma.sync + final MLP + skip -------------
// grid 128, block 256 (8 warps). Block: 32 q x 256 j. Warp: 32 q x 32 j
// as 2 (m16) x 4 (n8) tiles, K stepped by 8.
// dyn smem: s_a[32][260] (8320 f) + s_w[32][264] (8448 f) = 67072 B
#define SA_STRIDE 260
#define SW_STRIDE 264
__global__ void __launch_bounds__(256) gemm_kernel(
    const float* __restrict__ cell, const float* __restrict__ bi1,
    const float* __restrict__ Wi2, const float* __restrict__ bi2,
    float* __restrict__ out)
{
    extern __shared__ float sm[];
    float* s_a = sm;              // [32][260], row = q, col = c (tf32 values)
    float* s_w = sm + 8320;       // [32][264], row = c, col = j (tf32 values)
    __shared__ float s_cell[64];

    const int t = threadIdx.x;
    const int qb = blockIdx.x * 32;
    const int lane = t & 31, w = t >> 5;
    const int r = lane >> 2, cl = lane & 3;
    const int j0 = w * 32;
    const int bq = t >> 3, bh = t & 7;   // a-build roles: 32q x 8h

    if (t < 64) s_cell[t] = cell[qb * 2 + t];

    float cfrag[2][4][4];
#pragma unroll
    for (int mt = 0; mt < 2; mt++)
#pragma unroll
        for (int nt = 0; nt < 4; nt++)
#pragma unroll
            for (int i = 0; i < 4; i++) cfrag[mt][nt][i] = 0.f;

    for (int k = 0; k < 49; k++) {
        __syncthreads();
        // build A: s_a[q][c] = fv[pix][c] * attn[q][k][c/32], rounded to tf32
        {
            int pix = g_kidx[(qb + bq) * 49 + k];
            float aw = g_attn[((qb + bq) * 49 + k) * 8 + bh];
            const float4* fr = (const float4*)(g_fv + (pix < 0 ? 0 : pix) * 256 + bh * 32);
            float* dst = s_a + bq * SA_STRIDE + bh * 32;
#pragma unroll
            for (int i = 0; i < 8; i++) {
                float4 v = fr[i];
                if (pix < 0) v = make_float4(0.f, 0.f, 0.f, 0.f);
                float4 o;
                o.x = totf32(v.x * aw); o.y = totf32(v.y * aw);
                o.z = totf32(v.z * aw); o.w = totf32(v.w * aw);
                *(float4*)(dst + i * 4) = o;
            }
        }
        for (int sub = 0; sub < 8; sub++) {
            __syncthreads();
            { // stage W: s_w[c][j] = Wi1T[k*256 + sub*32 + c][j] (pre-rounded tf32)
                const float4* src4 = (const float4*)(g_Wi1T + (k * 256 + sub * 32) * 256);
#pragma unroll
                for (int i = 0; i < 8; i++) {
                    int idx = t + i * 256;
                    int c = idx >> 6, jj = idx & 63;
                    ((float4*)(s_w + c * SW_STRIDE))[jj] = src4[idx];
                }
            }
            __syncthreads();
            const unsigned* ua = (const unsigned*)s_a;
            const unsigned* uw = (const unsigned*)s_w;
#pragma unroll
            for (int ks = 0; ks < 4; ks++) {
                int c0 = ks * 8;
                unsigned afrag[2][4];
#pragma unroll
                for (int mt = 0; mt < 2; mt++) {
                    int row = mt * 16 + r;
                    afrag[mt][0] = ua[row * SA_STRIDE + c0 + cl];
                    afrag[mt][1] = ua[(row + 8) * SA_STRIDE + c0 + cl];
                    afrag[mt][2] = ua[row * SA_STRIDE + c0 + cl + 4];
                    afrag[mt][3] = ua[(row + 8) * SA_STRIDE + c0 + cl + 4];
                }
                unsigned bfrag[4][2];
#pragma unroll
                for (int nt = 0; nt < 4; nt++) {
                    int jc = j0 + nt * 8 + r;
                    bfrag[nt][0] = uw[(c0 + cl) * SW_STRIDE + jc];
                    bfrag[nt][1] = uw[(c0 + cl + 4) * SW_STRIDE + jc];
                }
#pragma unroll
                for (int mt = 0; mt < 2; mt++)
#pragma unroll
                    for (int nt = 0; nt < 4; nt++)
                        mma_tf32(cfrag[mt][nt], afrag[mt], bfrag[nt]);
            }
        }
    }
    __syncthreads();

    // epilogue: h = relu(acc + bi1 + w_cell0*ry + w_cell1*rx) -> s_h[32][260]
    float* s_h = sm;  // reuses s_a region
#pragma unroll
    for (int nt = 0; nt < 4; nt++) {
        int jg = j0 + nt * 8 + 2 * cl;
        float b0 = bi1[jg],     b1 = bi1[jg + 1];
        float w00 = g_Wi1T[12544 * 256 + jg], w01 = g_Wi1T[12544 * 256 + jg + 1];
        float w10 = g_Wi1T[12545 * 256 + jg], w11 = g_Wi1T[12545 * 256 + jg + 1];
#pragma unroll
        for (int mt = 0; mt < 2; mt++) {
#pragma unroll
            for (int half = 0; half < 2; half++) {
                int q = mt * 16 + r + half * 8;
                float ry = s_cell[q * 2 + 0] * 64.f, rx = s_cell[q * 2 + 1] * 64.f;
                float v0 = cfrag[mt][nt][half * 2 + 0] + b0 + w00 * ry + w10 * rx;
                float v1 = cfrag[mt][nt][half * 2 + 1] + b1 + w01 * ry + w11 * rx;
                s_h[q * SA_STRIDE + jg] = fmaxf(v0, 0.f);
                s_h[q * SA_STRIDE + jg + 1] = fmaxf(v1, 0.f);
            }
        }
    }
    float* s_w2 = sm + 8320;
    for (int i = t; i < 768; i += 256) s_w2[i] = Wi2[i];
    __syncthreads();

    if (t < 96) {
        int q = t / 3, c = t % 3;
        float s = 0.f;
        for (int j = 0; j < 256; j++) s += s_h[q * SA_STRIDE + j] * s_w2[c * 256 + j];
        out[(qb + q) * 3 + c] = s + bi2[c] + g_skipv[(qb + q) * 3 + c];
    }
}

// ---------------- host ------------------------------------------------------
extern "C" void kernel_launch(void* const* d_in, const int* in_sizes, int n_in,
                              void* d_out, int out_size)
{
    const float* inp   = (const float*)d_in[0];
    const float* coord = (const float*)d_in[1];
    const float* cell  = (const float*)d_in[2];
    const float* W_enc = (const float*)d_in[3];
    const float* b_enc = (const float*)d_in[4];
    const float* W_ch  = (const float*)d_in[5];
    const float* b_ch  = (const float*)d_in[6];
    const float* W_q   = (const float*)d_in[7];
    const float* b_q   = (const float*)d_in[8];
    const float* W_k   = (const float*)d_in[9];
    const float* b_k   = (const float*)d_in[10];
    const float* W_v   = (const float*)d_in[11];
    const float* b_v   = (const float*)d_in[12];
    const float* W_off1= (const float*)d_in[13];
    const float* b_off1= (const float*)d_in[14];
    const float* ln_g  = (const float*)d_in[15];
    const float* ln_b  = (const float*)d_in[16];
    const float* W_off2= (const float*)d_in[17];
    const float* Wc1   = (const float*)d_in[18];
    const float* bc1   = (const float*)d_in[19];
    const float* Wc2   = (const float*)d_in[20];
    const float* bc2   = (const float*)d_in[21];
    const float* Wi1   = (const float*)d_in[22];
    const float* bi1   = (const float*)d_in[23];
    const float* Wi2   = (const float*)d_in[24];
    const float* bi2   = (const float*)d_in[25];
    float* out = (float*)d_out;

    void* p;
    cudaGetSymbolAddress(&p, g_enc);    float* enc = (float*)p;
    cudaGetSymbolAddress(&p, g_feat);   float* feat = (float*)p;
    cudaGetSymbolAddress(&p, g_fq);     float* fq = (float*)p;
    cudaGetSymbolAddress(&p, g_fk);     float* fk = (float*)p;
    cudaGetSymbolAddress(&p, g_fv);     float* fv = (float*)p;
    cudaGetSymbolAddress(&p, g_off1);   float* off1 = (float*)p;
    cudaGetSymbolAddress(&p, g_act);    float* act = (float*)p;
    cudaGetSymbolAddress(&p, g_offmap); float* offmap = (float*)p;
    cudaGetSymbolAddress(&p, g_Wi1T);   float* wi1t = (float*)p;
    cudaGetSymbolAddress(&p, g_Wc1T);   float* wc1t = (float*)p;
    cudaGetSymbolAddress(&p, g_Wc2T);   float* wc2t = (float*)p;

    dim3 tb(32, 8);
    transpose_kernel<<<dim3(393, 8), tb>>>(Wi1, wi1t, 256, 12546, 1);
    transpose_kernel<<<dim3(4, 8), tb>>>(Wc1, wc1t, 256, 98, 0);
    transpose_kernel<<<dim3(8, 2), tb>>>(Wc2, wc2t, 49, 256, 0);

    conv3x3_kernel<3, 64, true, false><<<dim3(4, 4, 4), 128>>>(inp, W_enc, b_enc, enc);
    conv3x3_kernel<64, 256, false, false><<<dim3(4, 4, 16), 128>>>(enc, W_ch, b_ch, feat);
    conv3x3_kernel<256, 256, false, true><<<dim3(4, 4, 16), 128>>>(feat, W_q, b_q, fq);
    conv3x3_kernel<256, 256, false, true><<<dim3(4, 4, 16), 128>>>(feat, W_k, b_k, fk);
    conv3x3_kernel<256, 256, false, true><<<dim3(4, 4, 16), 128>>>(feat, W_v, b_v, fv);
    conv5x5g_kernel<<<dim3(4, 4, 8), 256>>>(feat, W_off1, b_off1, off1);
    ln_gelu_kernel<<<512, 256>>>(off1, ln_g, ln_b, act);
    conv1x1_kernel<<<128, 128>>>(act, W_off2, offmap);
    qprep_kernel<<<4096, 256>>>(coord, inp, bc1, bc2);

    cudaFuncSetAttribute(gemm_kernel, cudaFuncAttributeMaxDynamicSharedMemorySize, 67072);
    gemm_kernel<<<128, 256, 67072>>>(cell, bi1, Wi2, bi2, out);
}